// round 16
// baseline (speedup 1.0000x reference)
#include <cuda_runtime.h>
#include <cuda_fp16.h>
#include <cstdint>

// out[(b*64+n), :] = x[(b*64+n), :] @ W[n] / 16
// x: [4096*64, 256] f32, W: [64, 256, 256] f32, out: [4096*64, 256] f32
#define NODES   64
#define FDIM    256
#define ODIM    256
#define NGRAPH  4096

#define BM 128          // graphs per CTA
#define BN 128          // output cols per CTA
#define KC 32           // k-chunk
#define NKC (FDIM / KC) // 8
#define NTHREADS 256    // 8 warps, 32x64 warp tiles

// SMEM rings
#define A32_ROW   128                           // 128B fp32, no pad (conflict-free per phase)
#define A32_STAGE (BM * A32_ROW)                // 16384
#define A32_NST   3
#define A16_ROW   80                            // 64B fp16 + 16B pad (ldmatrix conflict-free)
#define A16_STAGE (BM * A16_ROW)                // 10240
#define A16_NST   2
#define B_STAGE   8192                          // 512 uint4 = 32k x 128 cols fp16
#define B_NST     4

#define A16_OFF (A32_NST * A32_STAGE)                   // 49152
#define B_OFF   (A16_OFF + A16_NST * A16_STAGE)         // 69632
#define SMEM_BYTES (B_OFF + B_NST * B_STAGE)            // 102400

__device__ __forceinline__ uint32_t smem_u32(const void* p) {
    return (uint32_t)__cvta_generic_to_shared(p);
}
__device__ __forceinline__ void cp_async16(uint32_t s, const void* g) {
    asm volatile("cp.async.cg.shared.global [%0], [%1], 16;" :: "r"(s), "l"(g));
}
__device__ __forceinline__ uint32_t pack_h2(float a, float b) {
    __half2 h = __floats2half2_rn(a, b);
    return *reinterpret_cast<uint32_t*>(&h);
}

// Packed fp16 W fragments for mma.m16n8k16 (B operand), layout identical to R12:
// [n][chunk(8)][wn(0..3)][s(0..1)][j(0..3)][lane(0..31)] as uint4
__device__ uint4 Whp_g[NODES * NKC * 1024];   // 8 MB, L2-resident

__global__ void pack_w_kernel(const float* __restrict__ W) {
    __shared__ float sw[KC * ODIM];
    const int n = blockIdx.y;
    const int chunk = blockIdx.x;
    const int tid = threadIdx.x;
    const float4* src = (const float4*)(W + ((size_t)n * FDIM + chunk * KC) * ODIM);
    float4* dst = (float4*)sw;
    #pragma unroll
    for (int i = 0; i < 8; i++)
        dst[tid + i * 256] = src[tid + i * 256];
    __syncthreads();

    const float sc = 0.0625f;   // 1/sqrt(FDIM)
    uint4* outp = Whp_g + ((size_t)n * NKC + chunk) * 1024;
    #pragma unroll
    for (int i = 0; i < 4; i++) {
        int c = tid + i * 256;
        int lane = c & 31;
        int j    = (c >> 5) & 3;
        int s    = (c >> 7) & 1;
        int wn   = (c >> 8) & 3;
        int gid = lane >> 2, tig = lane & 3;
        int k0 = s * 16 + 2 * tig;
        int o0 = wn * 64 + 16 * j + gid;
        uint4 v;
        v.x = pack_h2(sw[k0 * ODIM + o0] * sc,       sw[(k0 + 1) * ODIM + o0] * sc);
        v.y = pack_h2(sw[(k0 + 8) * ODIM + o0] * sc, sw[(k0 + 9) * ODIM + o0] * sc);
        v.z = pack_h2(sw[k0 * ODIM + o0 + 8] * sc,       sw[(k0 + 1) * ODIM + o0 + 8] * sc);
        v.w = pack_h2(sw[(k0 + 8) * ODIM + o0 + 8] * sc, sw[(k0 + 9) * ODIM + o0 + 8] * sc);
        outp[c] = v;
    }
}

__global__ void __launch_bounds__(NTHREADS, 2)
linear_mlp_node_kernel(const float* __restrict__ x, float* __restrict__ out) {
    extern __shared__ char smem[];
    const uint32_t sBase = smem_u32(smem);

    const int tid   = threadIdx.x;
    const int btile = blockIdx.x;   // 0..31
    const int ntile = blockIdx.y;   // 0..1
    const int n     = blockIdx.z;   // 0..63

    const int warp = tid >> 5;      // 0..7
    const int lane = tid & 31;
    const int wm = warp & 3;        // rows wm*32..+31
    const int wn = warp >> 2;       // cols wn*64..+63
    const int gid = lane >> 2;
    const int tig = lane & 3;

    const uint4* WhpN = Whp_g + (size_t)n * NKC * 1024 + (size_t)ntile * 512;

    // commit group j: A fp32 chunk j (1024 float4) + B packed chunk j (512 uint4)
    auto commitG = [&](int kc) {
        const uint32_t dA = sBase + (kc % A32_NST) * A32_STAGE;
        #pragma unroll
        for (int i = 0; i < 4; i++) {
            int c = tid + i * NTHREADS;
            int row = c >> 3, c4 = c & 7;
            const float* g = x + ((size_t)(btile * BM + row) * NODES + n) * FDIM
                           + kc * KC + c4 * 4;
            cp_async16(dA + row * A32_ROW + c4 * 16, g);
        }
        const uint32_t dB = sBase + B_OFF + (kc % B_NST) * B_STAGE;
        const uint4* gB = WhpN + (size_t)kc * 1024;
        #pragma unroll
        for (int i = 0; i < 2; i++) {
            int c = tid + i * NTHREADS;
            cp_async16(dB + c * 16, gB + c);
        }
        asm volatile("cp.async.commit_group;" ::: "memory");
    };
    // convert A32 stage (kc%3) -> A16 stage (kc&1)
    auto convertA = [&](int kc) {
        const char* src = smem + (kc % A32_NST) * A32_STAGE;
        char* dst = smem + A16_OFF + (kc & 1) * A16_STAGE;
        #pragma unroll
        for (int i = 0; i < 4; i++) {
            int c = tid + i * NTHREADS;
            int row = c >> 3, c4 = c & 7;
            float4 v = *reinterpret_cast<const float4*>(src + row * A32_ROW + c4 * 16);
            uint2 h;
            h.x = pack_h2(v.x, v.y);
            h.y = pack_h2(v.z, v.w);
            *reinterpret_cast<uint2*>(dst + row * A16_ROW + c4 * 8) = h;
        }
    };
    // fragment loads for (chunk kc, k16-step s)
    auto loadFrags = [&](int kc, int s, uint32_t a[2][4], uint4 b[4]) {
        const uint32_t aBase = sBase + A16_OFF + (kc & 1) * A16_STAGE
                             + (wm * 32 + (lane & 15)) * A16_ROW + (lane >> 4) * 16 + s * 32;
        #pragma unroll
        for (int mt = 0; mt < 2; mt++) {
            asm volatile(
                "ldmatrix.sync.aligned.m8n8.x4.shared.b16 {%0,%1,%2,%3}, [%4];"
                : "=r"(a[mt][0]), "=r"(a[mt][1]), "=r"(a[mt][2]), "=r"(a[mt][3])
                : "r"(aBase + mt * (16 * A16_ROW)));
        }
        const uint4* bBase = (const uint4*)(smem + B_OFF + (kc % B_NST) * B_STAGE)
                           + wn * 256 + lane + s * 128;
        #pragma unroll
        for (int j = 0; j < 4; j++)
            b[j] = bBase[j * 32];
    };

    float acc[2][8][4];
    #pragma unroll
    for (int mt = 0; mt < 2; mt++)
        #pragma unroll
        for (int nt = 0; nt < 8; nt++)
            #pragma unroll
            for (int r = 0; r < 4; r++)
                acc[mt][nt][r] = 0.0f;

    auto mmaStep = [&](uint32_t a[2][4], uint4 b[4]) {
        #pragma unroll
        for (int mt = 0; mt < 2; mt++) {
            #pragma unroll
            for (int j = 0; j < 4; j++) {
                asm volatile(
                    "mma.sync.aligned.m16n8k16.row.col.f32.f16.f16.f32 "
                    "{%0,%1,%2,%3}, {%4,%5,%6,%7}, {%8,%9}, {%0,%1,%2,%3};"
                    : "+f"(acc[mt][2 * j][0]), "+f"(acc[mt][2 * j][1]),
                      "+f"(acc[mt][2 * j][2]), "+f"(acc[mt][2 * j][3])
                    : "r"(a[mt][0]), "r"(a[mt][1]), "r"(a[mt][2]), "r"(a[mt][3]),
                      "r"(b[j].x), "r"(b[j].y));
                asm volatile(
                    "mma.sync.aligned.m16n8k16.row.col.f32.f16.f16.f32 "
                    "{%0,%1,%2,%3}, {%4,%5,%6,%7}, {%8,%9}, {%0,%1,%2,%3};"
                    : "+f"(acc[mt][2 * j + 1][0]), "+f"(acc[mt][2 * j + 1][1]),
                      "+f"(acc[mt][2 * j + 1][2]), "+f"(acc[mt][2 * j + 1][3])
                    : "r"(a[mt][0]), "r"(a[mt][1]), "r"(a[mt][2]), "r"(a[mt][3]),
                      "r"(b[j].z), "r"(b[j].w));
            }
        }
    };

    // ---- prologue ----
    commitG(0);
    commitG(1);
    commitG(2);
    asm volatile("cp.async.wait_group 2;" ::: "memory");   // G0 done
    __syncthreads();
    convertA(0);
    asm volatile("cp.async.wait_group 1;" ::: "memory");   // G1 done
    __syncthreads();                                       // convert(0) visible

    uint32_t a0[2][4], a1[2][4];
    uint4 b0[4], b1[4];
    loadFrags(0, 0, a0, b0);

    for (int kc = 0; kc < NKC; kc++) {
        mmaStep(a0, b0);                    // chunk kc, s=0 — opens the iteration

        loadFrags(kc, 1, a1, b1);           // s=1 frags (stage-safe: covered by co-warp MMAs)
        if (kc + 3 < NKC)
            commitG(kc + 3);                // writes A32 stage kc%3 / B stage (kc+3)%4 — both safe
        if (kc + 1 < NKC)
            convertA(kc + 1);               // overlaps tensor work

        mmaStep(a1, b1);                    // chunk kc, s=1

        if (kc < NKC - 1) {
            if (kc + 3 < NKC)
                asm volatile("cp.async.wait_group 1;" ::: "memory");
            else
                asm volatile("cp.async.wait_group 0;" ::: "memory");
            __syncthreads();                // convert(kc+1) visible; rings rotate safely
            loadFrags(kc + 1, 0, a0, b0);   // only post-barrier work before next MMAs
        }
    }

    // epilogue (scale folded into W)
    #pragma unroll
    for (int mt = 0; mt < 2; mt++) {
        #pragma unroll
        for (int nt = 0; nt < 8; nt++) {
            int g0  = btile * BM + wm * 32 + mt * 16 + gid;
            int col = ntile * BN + wn * 64 + nt * 8 + tig * 2;
            size_t r0 = ((size_t)g0 * NODES + n) * ODIM + col;
            size_t r1 = ((size_t)(g0 + 8) * NODES + n) * ODIM + col;
            *reinterpret_cast<float2*>(out + r0) = make_float2(acc[mt][nt][0], acc[mt][nt][1]);
            *reinterpret_cast<float2*>(out + r1) = make_float2(acc[mt][nt][2], acc[mt][nt][3]);
        }
    }
}

extern "C" void kernel_launch(void* const* d_in, const int* in_sizes, int n_in,
                              void* d_out, int out_size) {
    const float* x = (const float*)d_in[0];
    // d_in[1] = batch indices (int64) — implied by layout, unused
    const float* W = (const float*)d_in[2];
    float* out = (float*)d_out;

    pack_w_kernel<<<dim3(NKC, NODES), 256>>>(W);

    cudaFuncSetAttribute(linear_mlp_node_kernel,
                         cudaFuncAttributeMaxDynamicSharedMemorySize, SMEM_BYTES);
    dim3 grid(NGRAPH / BM, ODIM / BN, NODES);   // (32, 2, 64)
    linear_mlp_node_kernel<<<grid, NTHREADS, SMEM_BYTES>>>(x, out);
}